// round 1
// baseline (speedup 1.0000x reference)
#include <cuda_runtime.h>
#include <math.h>

// SSKernelNPLR: H=256, S=256 (rep=1), N=64, R=1, CH=1, L=2048
#define HH 256
#define NN 64
#define LL 2048
#define LH 1025   // L/2 + 1

// Scratch for the frequency-domain kernel k_f[h][l] (complex64): 256*1025*8 = 2.1 MB
__device__ float2 g_kf[HH * LH];

// ---------------------------------------------------------------------------
// Kernel 1: Cauchy sum + Woodbury + bilinear factor -> k_f
//
// Per (h, l):  y = 2 tan(pi*l/L)   (z = i*y; 2/(1+omega) = 1 + i*y/2)
//   For each n, conjugate pair folded:
//     pair = [NR + i*P2*y] / [(K1 - y^2) + i*(K2*y)]
//   with (per h,n, dt folded in):
//     a = -exp(iwr)*dt, b = wim*dt, K1 = a^2+b^2, K2 = -2a
//     NR = -2(p*a + q*b)*dt, P2 = 2p*dt     (v = p + i q)
//   One rcp per (h,l,n), shared by the 4 numerators v00,v01,v10,v11.
// ---------------------------------------------------------------------------
__global__ void __launch_bounds__(256) cauchy_kernel(
    const float* __restrict__ Cin, const float* __restrict__ Bin,
    const float* __restrict__ Pin, const float* __restrict__ iwr,
    const float* __restrict__ wim, const float* __restrict__ logdt)
{
    __shared__ float2 sK[NN];      // (K1, K2)
    __shared__ float2 sV[4][NN];   // (NR, P2) for v00, v01, v10, v11

    const int h = blockIdx.x;
    const int tid = threadIdx.x;

    if (tid < NN) {
        const int n = tid;
        const int idx = h * NN + n;
        const float dt = expf(logdt[h]);
        const float a = -expf(iwr[idx]) * dt;
        const float b = wim[idx] * dt;
        sK[n] = make_float2(fmaf(a, a, b * b), -2.0f * a);

        const float Br = Bin[2*idx], Bi = Bin[2*idx+1];
        const float Cr = Cin[2*idx], Ci = Cin[2*idx+1];
        const float Pr = Pin[2*idx], Pi = Pin[2*idx+1];

        float p, q;
        // v00 = B*C
        p = Br*Cr - Bi*Ci;  q = Br*Ci + Bi*Cr;
        sV[0][n] = make_float2(-2.0f*(p*a + q*b)*dt, 2.0f*p*dt);
        // v01 = B*conj(P)
        p = Br*Pr + Bi*Pi;  q = Bi*Pr - Br*Pi;
        sV[1][n] = make_float2(-2.0f*(p*a + q*b)*dt, 2.0f*p*dt);
        // v10 = P*C
        p = Pr*Cr - Pi*Ci;  q = Pr*Ci + Pi*Cr;
        sV[2][n] = make_float2(-2.0f*(p*a + q*b)*dt, 2.0f*p*dt);
        // v11 = P*conj(P) = |P|^2  (q = 0)
        p = Pr*Pr + Pi*Pi;
        sV[3][n] = make_float2(-2.0f*(p*a)*dt, 2.0f*p*dt);
    }
    __syncthreads();

    const int by = blockIdx.y;                // split l-range across 2 blocks per h
    const int lend = by ? LH : 512;
    for (int l = by * 512 + tid; l < lend; l += 256) {
        float y = 2.0f * tanf((float)l * (3.14159265358979323846f / 2048.0f));
        // guard the l = L/2 pole; k_f(y) -> finite limit, insensitive for |y| >~ 1e7
        y = fminf(fmaxf(y, -3.0e7f), 3.0e7f);
        const float yy = y * y;

        float r0r = 0.f, r0i = 0.f, r1r = 0.f, r1i = 0.f;
        float r2r = 0.f, r2i = 0.f, r3r = 0.f, r3i = 0.f;

        #pragma unroll 8
        for (int n = 0; n < NN; n++) {
            const float2 kk = sK[n];
            const float dr = kk.x - yy;
            const float di = kk.y * y;
            const float inv = __frcp_rn(fmaf(dr, dr, di * di));
            const float cr = dr * inv;   // Re(conj(d))/|d|^2
            const float ci = di * inv;   // (result uses  re=Nr*cr+Ni*ci, im=Ni*cr-Nr*ci)

            float2 v; float Ni;
            v = sV[0][n]; Ni = v.y * y;
            r0r = fmaf(v.x, cr, fmaf( Ni, ci, r0r));
            r0i = fmaf( Ni, cr, fmaf(-v.x, ci, r0i));
            v = sV[1][n]; Ni = v.y * y;
            r1r = fmaf(v.x, cr, fmaf( Ni, ci, r1r));
            r1i = fmaf( Ni, cr, fmaf(-v.x, ci, r1i));
            v = sV[2][n]; Ni = v.y * y;
            r2r = fmaf(v.x, cr, fmaf( Ni, ci, r2r));
            r2i = fmaf( Ni, cr, fmaf(-v.x, ci, r2i));
            v = sV[3][n]; Ni = v.y * y;
            r3r = fmaf(v.x, cr, fmaf( Ni, ci, r3r));
            r3i = fmaf( Ni, cr, fmaf(-v.x, ci, r3i));
        }

        // Woodbury: kf = r00 - r01*r10/(1 + r11)
        const float dre = 1.0f + r3r;
        const float dim_ = r3i;
        const float dm = 1.0f / fmaf(dre, dre, dim_ * dim_);
        const float tr = r1r * r2r - r1i * r2i;
        const float ti = r1r * r2i + r1i * r2r;
        const float wr = (tr * dre + ti * dim_) * dm;
        const float wi = (ti * dre - tr * dim_) * dm;
        float kr = r0r - wr;
        float ki = r0i - wi;

        // * 2/(1+omega) = (1 + i*y/2)
        const float hy = 0.5f * y;
        g_kf[h * LH + l] = make_float2(kr - ki * hy, ki + kr * hy);
    }
}

// ---------------------------------------------------------------------------
// Kernel 2: irfft(k_f, n=2048) per h, via two-step DFT (2048 = 64 x 32).
//   X[l] = full Hermitian spectrum (X[2048-l] = conj(X[l]))
//   A[l1][tm] = sum_{l2<32} X[l1 + 64*l2] * e^{+2pi i l2 tm / 32}
//   k[t] = (1/2048) * Re( sum_{l1<64} A[l1][t&31] * e^{+2pi i l1 t / 2048} )
// Twiddles via per-thread rotation recurrence (no tables -> no bank conflicts).
// ---------------------------------------------------------------------------
__global__ void __launch_bounds__(256) irfft_kernel(float* __restrict__ out)
{
    __shared__ float2 sX[LL];       // 16 KB
    __shared__ float2 sA[64][32];   // 16 KB

    const int h = blockIdx.x;
    const int tid = threadIdx.x;
    const float2* kf = &g_kf[h * LH];

    // Build full Hermitian spectrum
    for (int j = tid; j < LL; j += 256) {
        float2 v;
        if (j <= 1024) {
            v = kf[j];
        } else {
            float2 w = kf[2048 - j];
            v = make_float2(w.x, -w.y);
        }
        sX[j] = v;
    }
    __syncthreads();

    // Step A
    {
        const int tm = tid & 31;
        float rs, rc;
        sincospif((float)tm * (1.0f / 16.0f), &rs, &rc);  // e^{2pi i tm/32}
        #pragma unroll
        for (int pass = 0; pass < 8; pass++) {
            const int l1 = pass * 8 + (tid >> 5);
            float cr = 1.0f, ci = 0.0f;
            float ar = 0.0f, ai = 0.0f;
            #pragma unroll 8
            for (int l2 = 0; l2 < 32; l2++) {
                const float2 x = sX[l1 + 64 * l2];   // lane-uniform -> broadcast
                ar = fmaf(x.x, cr, fmaf(-x.y, ci, ar));
                ai = fmaf(x.x, ci, fmaf( x.y, cr, ai));
                const float ncr = fmaf(cr, rc, -ci * rs);
                const float nci = fmaf(cr, rs,  ci * rc);
                cr = ncr; ci = nci;
            }
            sA[l1][tm] = make_float2(ar, ai);        // lane = tm -> conflict-free
        }
    }
    __syncthreads();

    // Step B
    for (int t = tid; t < LL; t += 256) {
        const int tm = t & 31;
        float rs, rc;
        sincospif((float)t * (1.0f / 1024.0f), &rs, &rc);  // e^{2pi i t/2048}
        float cr = 1.0f, ci = 0.0f;
        float acc = 0.0f;
        #pragma unroll 8
        for (int l1 = 0; l1 < 64; l1++) {
            const float2 a = sA[l1][tm];             // lane = tm -> conflict-free
            acc = fmaf(a.x, cr, fmaf(-a.y, ci, acc));
            const float ncr = fmaf(cr, rc, -ci * rs);
            const float nci = fmaf(cr, rs,  ci * rc);
            cr = ncr; ci = nci;
        }
        out[h * LL + t] = acc * (1.0f / 2048.0f);
    }
}

// ---------------------------------------------------------------------------
// Inputs (metadata order = setup_inputs dict order):
//   0: C (1,256,64,2) f32   1: B (1,256,64,2) f32   2: P (1,256,64,2) f32
//   3: inv_w_real (256,64)  4: w_imag (256,64)      5: log_dt (256,)   6: L (scalar, ignored)
// Output: (1, 256, 2048) f32
// ---------------------------------------------------------------------------
extern "C" void kernel_launch(void* const* d_in, const int* in_sizes, int n_in,
                              void* d_out, int out_size)
{
    const float* C     = (const float*)d_in[0];
    const float* B     = (const float*)d_in[1];
    const float* P     = (const float*)d_in[2];
    const float* iwr   = (const float*)d_in[3];
    const float* wimag = (const float*)d_in[4];
    const float* logdt = (const float*)d_in[5];
    float* out = (float*)d_out;

    dim3 grid1(HH, 2);
    cauchy_kernel<<<grid1, 256>>>(C, B, P, iwr, wimag, logdt);
    irfft_kernel<<<HH, 256>>>(out);
}

// round 2
// speedup vs baseline: 1.6097x; 1.6097x over previous
#include <cuda_runtime.h>
#include <math.h>

// SSKernelNPLR: H=256, S=256 (rep=1), N=64, R=1, CH=1, L=2048
#define HH 256
#define NN 64
#define LL 2048
#define LH 1025   // L/2 + 1

// Scratch for frequency-domain kernel k_f[h][l] (complex64)
__device__ float2 g_kf[HH * LH];

// ---- packed f32x2 helpers (sm_100+) ----
__device__ __forceinline__ unsigned long long pack2(float lo, float hi) {
    unsigned long long r;
    asm("mov.b64 %0, {%1, %2};" : "=l"(r) : "f"(lo), "f"(hi));
    return r;
}
__device__ __forceinline__ void unpack2(unsigned long long v, float& lo, float& hi) {
    asm("mov.b64 {%0, %1}, %2;" : "=f"(lo), "=f"(hi) : "l"(v));
}
__device__ __forceinline__ unsigned long long ffma2(
    unsigned long long a, unsigned long long b, unsigned long long c) {
    unsigned long long d;
    asm("fma.rn.f32x2 %0, %1, %2, %3;" : "=l"(d) : "l"(a), "l"(b), "l"(c));
    return d;
}
__device__ __forceinline__ float frcp_a(float x) {
    float r;
    asm("rcp.approx.f32 %0, %1;" : "=f"(r) : "f"(x));
    return r;
}

// ---------------------------------------------------------------------------
// Kernel 1: Cauchy sum + Woodbury + bilinear factor -> k_f
// Per (h,l):  y = 2 tan(pi*l/L); z = i*y; 2/(1+omega) = 1 + i*y/2
// Conjugate-pair-folded term per n:  (Nr + i*vy*y) / (dr + i*di)
//   dr = K1 - y^2, di = K2*y; with 1/d = cr - i*ci:
//   re += Nr*cr + vy*(y*ci),  im += vy*(y*cr) - Nr*ci
// Packed: acc=(re,im);  acc = fma((Nr,Nr),(cr,-ci),acc); acc = fma((vy,vy),(u,w),acc)
// ---------------------------------------------------------------------------
__global__ void __launch_bounds__(256) cauchy_kernel(
    const float* __restrict__ Cin, const float* __restrict__ Bin,
    const float* __restrict__ Pin, const float* __restrict__ iwr,
    const float* __restrict__ wim, const float* __restrict__ logdt)
{
    __shared__ float2 sK[NN];        // (K1, K2)
    __shared__ float4 sP[4][NN];     // (Nr, Nr, vy, vy) for v00,v01,v10,v11

    const int h = blockIdx.x;
    const int tid = threadIdx.x;

    if (tid < NN) {
        const int n = tid;
        const int idx = h * NN + n;
        const float dt = expf(logdt[h]);
        const float a = -expf(iwr[idx]) * dt;
        const float b = wim[idx] * dt;
        sK[n] = make_float2(fmaf(a, a, b * b), -2.0f * a);

        const float Br = Bin[2*idx], Bi = Bin[2*idx+1];
        const float Cr = Cin[2*idx], Ci = Cin[2*idx+1];
        const float Pr = Pin[2*idx], Pi = Pin[2*idx+1];

        float p, q, Nr, vy;
        // v00 = B*C
        p = Br*Cr - Bi*Ci;  q = Br*Ci + Bi*Cr;
        Nr = -2.0f*(p*a + q*b)*dt; vy = 2.0f*p*dt;
        sP[0][n] = make_float4(Nr, Nr, vy, vy);
        // v01 = B*conj(P)
        p = Br*Pr + Bi*Pi;  q = Bi*Pr - Br*Pi;
        Nr = -2.0f*(p*a + q*b)*dt; vy = 2.0f*p*dt;
        sP[1][n] = make_float4(Nr, Nr, vy, vy);
        // v10 = P*C
        p = Pr*Cr - Pi*Ci;  q = Pr*Ci + Pi*Cr;
        Nr = -2.0f*(p*a + q*b)*dt; vy = 2.0f*p*dt;
        sP[2][n] = make_float4(Nr, Nr, vy, vy);
        // v11 = |P|^2 (q=0)
        p = Pr*Pr + Pi*Pi;
        Nr = -2.0f*p*a*dt; vy = 2.0f*p*dt;
        sP[3][n] = make_float4(Nr, Nr, vy, vy);
    }
    __syncthreads();

    const ulonglong2* __restrict__ p0 = reinterpret_cast<const ulonglong2*>(sP[0]);
    const ulonglong2* __restrict__ p1 = reinterpret_cast<const ulonglong2*>(sP[1]);
    const ulonglong2* __restrict__ p2 = reinterpret_cast<const ulonglong2*>(sP[2]);
    const ulonglong2* __restrict__ p3 = reinterpret_cast<const ulonglong2*>(sP[3]);

    for (int l = blockIdx.y * 256 + tid; l < LH; l += 1024) {
        float y = 2.0f * tanf((float)l * (3.14159265358979323846f / 2048.0f));
        y = fminf(fmaxf(y, -3.0e7f), 3.0e7f);   // guard l = L/2 pole
        const float yy = y * y;

        unsigned long long a0 = 0ull, a1 = 0ull, a2 = 0ull, a3 = 0ull;

        #pragma unroll 8
        for (int n = 0; n < NN; n++) {
            const float2 kk = sK[n];
            const float dr  = kk.x - yy;
            const float di  = kk.y * y;
            const float inv = frcp_a(fmaf(dr, dr, di * di));
            const float cr  = dr * inv;
            const float nci = -di * inv;      // -ci
            const float u   = -y * nci;       //  y*ci
            const float w   =  y * cr;
            const unsigned long long Pc = pack2(cr, nci);
            const unsigned long long Pu = pack2(u, w);

            ulonglong2 q;
            q = p0[n]; a0 = ffma2(q.x, Pc, a0); a0 = ffma2(q.y, Pu, a0);
            q = p1[n]; a1 = ffma2(q.x, Pc, a1); a1 = ffma2(q.y, Pu, a1);
            q = p2[n]; a2 = ffma2(q.x, Pc, a2); a2 = ffma2(q.y, Pu, a2);
            q = p3[n]; a3 = ffma2(q.x, Pc, a3); a3 = ffma2(q.y, Pu, a3);
        }

        float r0r, r0i, r1r, r1i, r2r, r2i, r3r, r3i;
        unpack2(a0, r0r, r0i);
        unpack2(a1, r1r, r1i);
        unpack2(a2, r2r, r2i);
        unpack2(a3, r3r, r3i);

        // Woodbury: kf = r00 - r01*r10/(1 + r11)
        const float dre  = 1.0f + r3r;
        const float dim_ = r3i;
        const float dm = frcp_a(fmaf(dre, dre, dim_ * dim_));
        const float tr = r1r * r2r - r1i * r2i;
        const float ti = r1r * r2i + r1i * r2r;
        const float wr = (tr * dre + ti * dim_) * dm;
        const float wi = (ti * dre - tr * dim_) * dm;
        const float kr = r0r - wr;
        const float ki = r0i - wi;

        // * 2/(1+omega) = (1 + i*y/2)
        const float hy = 0.5f * y;
        g_kf[h * LH + l] = make_float2(kr - ki * hy, ki + kr * hy);
    }
}

// ---------------------------------------------------------------------------
// Kernel 2: irfft(k_f, n=2048) via real-packing to a 1024-point complex IDFT.
//   E[k] = (X[k] + conj(X[1024-k]))/2
//   O[k] = e^{2pi i k/2048} (X[k] - conj(X[1024-k]))/2
//   Z[k] = (E[k] + i O[k]) / 1024          (k = 0..1023)
//   z[n] = sum_k Z[k] e^{2pi i k n / 1024} ;  k[2n]=Re z, k[2n+1]=Im z
// 1024-pt IDFT as 32x32 two-step:
//   A[k1][m] = sum_{k2<32} Z[k1+32k2] e^{2pi i k2 m/32}
//   z[n]     = sum_{k1<32} A[k1][n&31]   e^{2pi i k1 n/1024}
// ---------------------------------------------------------------------------
__global__ void __launch_bounds__(256) irfft_kernel(float* __restrict__ out)
{
    __shared__ float2 sZ[1024];     // 8 KB
    __shared__ float2 sA[32][32];   // 8 KB

    const int h = blockIdx.x;
    const int tid = threadIdx.x;
    const float2* __restrict__ kf = &g_kf[h * LH];

    // Prep: build packed spectrum Z
    for (int k = tid; k < 1024; k += 256) {
        const float2 Xk = kf[k];
        float2 Xc = kf[1024 - k];
        Xc.y = -Xc.y;                              // conj
        const float sr = Xk.x + Xc.x, si = Xk.y + Xc.y;
        const float er = Xk.x - Xc.x, ei = Xk.y - Xc.y;
        float ts, tc;
        sincospif((float)k * (1.0f / 1024.0f), &ts, &tc);   // e^{i pi k/1024}
        const float Or = tc * er - ts * ei;
        const float Oi = tc * ei + ts * er;
        sZ[k] = make_float2((sr - Oi) * (1.0f / 2048.0f),
                            (si + Or) * (1.0f / 2048.0f));
    }
    __syncthreads();

    // Step A
    {
        const int m = tid & 31;
        float rs, rc;
        sincospif((float)m * (1.0f / 16.0f), &rs, &rc);     // e^{2pi i m/32}
        #pragma unroll
        for (int pass = 0; pass < 4; pass++) {
            const int k1 = pass * 8 + (tid >> 5);
            float cr = 1.0f, ci = 0.0f, ar = 0.0f, ai = 0.0f;
            #pragma unroll 8
            for (int k2 = 0; k2 < 32; k2++) {
                const float2 x = sZ[k1 + 32 * k2];          // lane-uniform -> broadcast
                ar = fmaf(x.x, cr, fmaf(-x.y, ci, ar));
                ai = fmaf(x.x, ci, fmaf( x.y, cr, ai));
                const float ncr = fmaf(cr, rc, -ci * rs);
                const float nci = fmaf(cr, rs,  ci * rc);
                cr = ncr; ci = nci;
            }
            sA[k1][m] = make_float2(ar, ai);                // lane = m -> conflict-free
        }
    }
    __syncthreads();

    // Step B
    float2* __restrict__ out2 = reinterpret_cast<float2*>(out + h * LL);
    for (int n = tid; n < 1024; n += 256) {
        const int tm = n & 31;
        float rs, rc;
        sincospif((float)n * (1.0f / 512.0f), &rs, &rc);    // e^{2pi i n/1024}
        float cr = 1.0f, ci = 0.0f, zr = 0.0f, zi = 0.0f;
        #pragma unroll 8
        for (int k1 = 0; k1 < 32; k1++) {
            const float2 a = sA[k1][tm];                    // lane = tm -> conflict-free
            zr = fmaf(a.x, cr, fmaf(-a.y, ci, zr));
            zi = fmaf(a.x, ci, fmaf( a.y, cr, zi));
            const float ncr = fmaf(cr, rc, -ci * rs);
            const float nci = fmaf(cr, rs,  ci * rc);
            cr = ncr; ci = nci;
        }
        out2[n] = make_float2(zr, zi);                      // k[2n], k[2n+1]
    }
}

// ---------------------------------------------------------------------------
// Inputs: 0:C 1:B 2:P 3:inv_w_real 4:w_imag 5:log_dt 6:L(ignored)
// Output: (1, 256, 2048) f32
// ---------------------------------------------------------------------------
extern "C" void kernel_launch(void* const* d_in, const int* in_sizes, int n_in,
                              void* d_out, int out_size)
{
    const float* C     = (const float*)d_in[0];
    const float* B     = (const float*)d_in[1];
    const float* P     = (const float*)d_in[2];
    const float* iwr   = (const float*)d_in[3];
    const float* wimag = (const float*)d_in[4];
    const float* logdt = (const float*)d_in[5];
    float* out = (float*)d_out;

    dim3 grid1(HH, 4);
    cauchy_kernel<<<grid1, 256>>>(C, B, P, iwr, wimag, logdt);
    irfft_kernel<<<HH, 256>>>(out);
}